// round 1
// baseline (speedup 1.0000x reference)
#include <cuda_runtime.h>
#include <cuda_bf16.h>
#include <math.h>

// ---------------- problem constants ----------------
#define Bsz 4
#define Lseq 2048
#define DM 1024
#define DSTATE 64
#define DCONV 4
#define DI 2048          // D_INNER
#define NH 32            // NHEADS
#define HD 64            // HEADDIM
#define CONVD 2176       // CONV_DIM = DI + 2*DSTATE
#define DIP 4256         // D_IN_PROJ
#define NTOK (Bsz*Lseq)  // 8192

// ---------------- scratch (static device memory; no allocations) ----------------
__device__ float g_zxbcdt[(size_t)NTOK * DIP];          // 8192 x 4256
__device__ float g_act[2ull * NTOK * CONVD];            // per-direction conv output (logical time order)
__device__ float2 g_dtA[2ull * NTOK * NH];              // (dA, dt) per (d,b,t,h)
__device__ float g_y[2ull * NTOK * DI];                 // per-direction y (physical order)
__device__ float g_cat[(size_t)NTOK * (2*DM)];          // concat of out_proj results

// ---------------- generic SGEMM: C[M,N] = A[M,K] @ B[K,N] (+bias) ----------------
// Tiles: 128x128x16, 256 threads, 8x8 per thread.
template<bool BIAS>
__global__ __launch_bounds__(256)
void sgemm_kernel(const float* __restrict__ A, const float* __restrict__ Bg,
                  float* __restrict__ C, const float* __restrict__ bias,
                  int M, int N, int K, int ldc)
{
    __shared__ float As[16][132];
    __shared__ float Bs[16][128];

    const int tid = threadIdx.x;
    const int tx = tid & 15;        // 0..15 -> col groups
    const int ty = tid >> 4;        // 0..15 -> row groups
    const int bm = blockIdx.y * 128;
    const int bn = blockIdx.x * 128;

    const int arow = tid >> 2;         // 0..63
    const int acol = (tid & 3) << 2;   // 0,4,8,12
    const int brow = tid >> 5;         // 0..7
    const int bcol = (tid & 31) << 2;  // 0..124

    float acc[8][8];
#pragma unroll
    for (int i = 0; i < 8; i++)
#pragma unroll
        for (int j = 0; j < 8; j++) acc[i][j] = 0.f;

    for (int k0 = 0; k0 < K; k0 += 16) {
        // load A tile (transposed into As[k][m])
#pragma unroll
        for (int r = 0; r < 2; r++) {
            int row = arow + r * 64;
            float4 av = *(const float4*)(A + (size_t)(bm + row) * K + k0 + acol);
            As[acol + 0][row] = av.x;
            As[acol + 1][row] = av.y;
            As[acol + 2][row] = av.z;
            As[acol + 3][row] = av.w;
        }
        // load B tile
#pragma unroll
        for (int r = 0; r < 2; r++) {
            int kr = brow + r * 8;
            float4 bv = make_float4(0.f, 0.f, 0.f, 0.f);
            if (bn + bcol < N)
                bv = *(const float4*)(Bg + (size_t)(k0 + kr) * N + bn + bcol);
            *(float4*)&Bs[kr][bcol] = bv;
        }
        __syncthreads();

#pragma unroll
        for (int kk = 0; kk < 16; kk++) {
            float a[8], b[8];
            float4 t0 = *(const float4*)&As[kk][ty * 4];
            float4 t1 = *(const float4*)&As[kk][64 + ty * 4];
            a[0]=t0.x; a[1]=t0.y; a[2]=t0.z; a[3]=t0.w;
            a[4]=t1.x; a[5]=t1.y; a[6]=t1.z; a[7]=t1.w;
            float4 u0 = *(const float4*)&Bs[kk][tx * 4];
            float4 u1 = *(const float4*)&Bs[kk][64 + tx * 4];
            b[0]=u0.x; b[1]=u0.y; b[2]=u0.z; b[3]=u0.w;
            b[4]=u1.x; b[5]=u1.y; b[6]=u1.z; b[7]=u1.w;
#pragma unroll
            for (int i = 0; i < 8; i++)
#pragma unroll
                for (int j = 0; j < 8; j++)
                    acc[i][j] += a[i] * b[j];
        }
        __syncthreads();
    }

    // epilogue
#pragma unroll
    for (int i = 0; i < 8; i++) {
        int row = bm + (i >> 2) * 64 + (ty << 2) + (i & 3);
#pragma unroll
        for (int half = 0; half < 2; half++) {
            int col = bn + half * 64 + (tx << 2);
            if (col < N) {
                float4 v;
                v.x = acc[i][half * 4 + 0];
                v.y = acc[i][half * 4 + 1];
                v.z = acc[i][half * 4 + 2];
                v.w = acc[i][half * 4 + 3];
                if (BIAS) {
                    v.x += bias[col + 0];
                    v.y += bias[col + 1];
                    v.z += bias[col + 2];
                    v.w += bias[col + 3];
                }
                *(float4*)(C + (size_t)row * ldc + col) = v;
            }
        }
    }
}

// ---------------- conv + silu + dt softplus/dA ----------------
// One block per (d, b, t) in LOGICAL time; writes g_act in logical order.
__global__ __launch_bounds__(256)
void conv_silu_kernel(const float* __restrict__ conv_w, const float* __restrict__ conv_b,
                      const float* __restrict__ dt_bias, const float* __restrict__ A_log)
{
    const int idx = blockIdx.x;
    const int t = idx & (Lseq - 1);
    const int b = (idx >> 11) & 3;
    const int d = idx >> 13;

    // physical indices of taps (logical t-3 .. t)
    int ph[4];
#pragma unroll
    for (int k = 0; k < 4; k++) {
        int j = t - 3 + k;
        ph[k] = (j < 0) ? -1 : (d ? (Lseq - 1 - j) : j);
    }

    float* outrow = g_act + ((size_t)(d * Bsz + b) * Lseq + t) * CONVD;

    for (int c = threadIdx.x; c < CONVD; c += 256) {
        float acc = conv_b[c];
#pragma unroll
        for (int k = 0; k < 4; k++) {
            if (ph[k] >= 0) {
                float v = g_zxbcdt[((size_t)b * Lseq + ph[k]) * DIP + DI + c];
                acc += v * conv_w[c * 4 + k];
            }
        }
        // silu
        float s = acc / (1.f + expf(-acc));
        outrow[c] = s;
    }

    if (threadIdx.x < NH) {
        int h = threadIdx.x;
        int pl = d ? (Lseq - 1 - t) : t;
        float raw = g_zxbcdt[((size_t)b * Lseq + pl) * DIP + (DIP - NH) + h] + dt_bias[h];
        float dt = (raw > 20.f) ? raw : log1pf(expf(raw));
        float A = -expf(A_log[h]);
        float dA = expf(dt * A);
        g_dtA[((size_t)(d * Bsz + b) * Lseq + t) * NH + h] = make_float2(dA, dt);
    }
}

// ---------------- sequential selective scan ----------------
// One CTA per (d, b, h). 512 threads: warp w owns p in {4w..4w+3}; within a warp,
// 8-lane group g=(lane>>3) -> p = 4w+g, lane&7 selects n block: n = (lane&7)*8 + j, j=0..7.
// y reduction: 3 shfl_xor within 8-lane groups.
__global__ __launch_bounds__(512)
void scan_kernel(const float* __restrict__ Dvec)
{
    const int h = blockIdx.x & 31;
    const int b = (blockIdx.x >> 5) & 3;
    const int d = blockIdx.x >> 7;

    const int lane = threadIdx.x & 31;
    const int w = threadIdx.x >> 5;
    const int p = w * 4 + (lane >> 3);
    const int n0 = (lane & 7) * 8;

    const float* actb = g_act + (size_t)(d * Bsz + b) * Lseq * CONVD;
    const float2* dtA = g_dtA + (size_t)(d * Bsz + b) * Lseq * NH;
    float* yb = g_y + (size_t)(d * Bsz + b) * Lseq * DI;

    const float Dh = Dvec[h];
    const bool writer = ((lane & 7) == 0);

    float S[8];
#pragma unroll
    for (int j = 0; j < 8; j++) S[j] = 0.f;

    for (int t = 0; t < Lseq; t++) {
        const float* a = actb + (size_t)t * CONVD;
        float4 B0 = *(const float4*)(a + DI + n0);
        float4 B1 = *(const float4*)(a + DI + n0 + 4);
        float4 C0 = *(const float4*)(a + DI + DSTATE + n0);
        float4 C1 = *(const float4*)(a + DI + DSTATE + n0 + 4);
        float xv = a[h * HD + p];
        float2 ad = dtA[t * NH + h];
        float dA = ad.x;
        float dtx = ad.y * xv;

        float y = 0.f;
        S[0] = S[0] * dA + dtx * B0.x; y += S[0] * C0.x;
        S[1] = S[1] * dA + dtx * B0.y; y += S[1] * C0.y;
        S[2] = S[2] * dA + dtx * B0.z; y += S[2] * C0.z;
        S[3] = S[3] * dA + dtx * B0.w; y += S[3] * C0.w;
        S[4] = S[4] * dA + dtx * B1.x; y += S[4] * C1.x;
        S[5] = S[5] * dA + dtx * B1.y; y += S[5] * C1.y;
        S[6] = S[6] * dA + dtx * B1.z; y += S[6] * C1.z;
        S[7] = S[7] * dA + dtx * B1.w; y += S[7] * C1.w;

        y += __shfl_xor_sync(0xFFFFFFFFu, y, 1);
        y += __shfl_xor_sync(0xFFFFFFFFu, y, 2);
        y += __shfl_xor_sync(0xFFFFFFFFu, y, 4);

        if (writer) {
            int pl = d ? (Lseq - 1 - t) : t;
            yb[(size_t)pl * DI + h * HD + p] = y + Dh * xv;
        }
    }
}

// ---------------- gate (silu(z)) + RMSNorm, in place on g_y ----------------
// One block per (d, b, l) in PHYSICAL order.
__global__ __launch_bounds__(256)
void gate_norm_kernel(const float* __restrict__ norm_w)
{
    const int idx = blockIdx.x;
    const int l = idx & (Lseq - 1);
    const int b = (idx >> 11) & 3;
    const int d = idx >> 13;

    float* yrow = g_y + ((size_t)(d * Bsz + b) * Lseq + l) * DI;
    const float* zrow = g_zxbcdt + ((size_t)b * Lseq + l) * DIP;

    float vals[8];
    float ss = 0.f;
#pragma unroll
    for (int i = 0; i < 8; i++) {
        int c = threadIdx.x + i * 256;
        float yv = yrow[c];
        float z = zrow[c];
        float g = yv * (z / (1.f + expf(-z)));
        vals[i] = g;
        ss += g * g;
    }

    // block reduce ss
    __shared__ float red[8];
#pragma unroll
    for (int m = 16; m > 0; m >>= 1) ss += __shfl_xor_sync(0xFFFFFFFFu, ss, m);
    if ((threadIdx.x & 31) == 0) red[threadIdx.x >> 5] = ss;
    __syncthreads();
    if (threadIdx.x < 8) {
        float v = red[threadIdx.x];
#pragma unroll
        for (int m = 4; m > 0; m >>= 1) v += __shfl_xor_sync(0xFFu, v, m);
        if (threadIdx.x == 0) red[0] = v;
    }
    __syncthreads();
    float scale = rsqrtf(red[0] * (1.f / DI) + 1e-5f);

#pragma unroll
    for (int i = 0; i < 8; i++) {
        int c = threadIdx.x + i * 256;
        yrow[c] = vals[i] * scale * norm_w[c];
    }
}

// ---------------- launch ----------------
extern "C" void kernel_launch(void* const* d_in, const int* in_sizes, int n_in,
                              void* d_out, int out_size)
{
    const float* x          = (const float*)d_in[0];
    const float* in_proj_w  = (const float*)d_in[1];
    const float* conv_w     = (const float*)d_in[2];
    const float* conv_b     = (const float*)d_in[3];
    const float* dt_bias    = (const float*)d_in[4];
    const float* A_log      = (const float*)d_in[5];
    const float* Dvec       = (const float*)d_in[6];
    const float* norm_w     = (const float*)d_in[7];
    const float* out_proj_w = (const float*)d_in[8];
    const float* proj_w     = (const float*)d_in[9];
    const float* proj_b     = (const float*)d_in[10];
    float* out = (float*)d_out;

    float* zp;  cudaGetSymbolAddress((void**)&zp, g_zxbcdt);
    float* yp;  cudaGetSymbolAddress((void**)&yp, g_y);
    float* cp;  cudaGetSymbolAddress((void**)&cp, g_cat);

    // 1) in_proj GEMM (shared across directions): zxbcdt = x @ in_proj_w
    {
        dim3 grid((DIP + 127) / 128, NTOK / 128);
        sgemm_kernel<false><<<grid, 256>>>(x, in_proj_w, zp, nullptr,
                                           NTOK, DIP, DM, DIP);
    }

    // 2) conv + silu + dt prep, both directions (logical order)
    conv_silu_kernel<<<2 * NTOK, 256>>>(conv_w, conv_b, dt_bias, A_log);

    // 3) selective scan, 256 CTAs
    scan_kernel<<<2 * Bsz * NH, 512>>>(Dvec);

    // 4) gate + RMSNorm in place
    gate_norm_kernel<<<2 * NTOK, 256>>>(norm_w);

    // 5) out_proj per direction into concat buffer
    {
        dim3 grid((DM + 127) / 128, NTOK / 128);
        sgemm_kernel<false><<<grid, 256>>>(yp, out_proj_w, cp, nullptr,
                                           NTOK, DM, DI, 2 * DM);
        sgemm_kernel<false><<<grid, 256>>>(yp + (size_t)NTOK * DI, out_proj_w,
                                           cp + DM, nullptr,
                                           NTOK, DM, DI, 2 * DM);
    }

    // 6) final projection with bias
    {
        dim3 grid((DM + 127) / 128, NTOK / 128);
        sgemm_kernel<true><<<grid, 256>>>(cp, proj_w, out, proj_b,
                                          NTOK, DM, 2 * DM, DM);
    }
}

// round 6
// speedup vs baseline: 1.2100x; 1.2100x over previous
#include <cuda_runtime.h>
#include <cuda_bf16.h>
#include <mma.h>
#include <cstdint>
#include <math.h>

using namespace nvcuda;

// ---------------- problem constants ----------------
#define Bsz 4
#define Lseq 2048
#define DM 1024
#define DSTATE 64
#define DI 2048          // D_INNER
#define NH 32            // NHEADS
#define HD 64            // HEADDIM
#define CONVD 2176       // CONV_DIM
#define DIP 4256         // D_IN_PROJ
#define NTOK (Bsz*Lseq)  // 8192

// ---------------- scratch (static device memory; no allocations) ----------------
__device__ float g_zxbcdt[(size_t)NTOK * DIP];
__device__ float g_act[2ull * NTOK * CONVD];
__device__ float2 g_dtA[2ull * NTOK * NH];
__device__ float g_y[2ull * NTOK * DI];
__device__ float g_cat[(size_t)NTOK * (2*DM)];
// transposed weights: inT[4256,1024], outT[1024,2048], projT[1024,2048]
__device__ float g_wT[4256*1024 + 1024*2048 + 1024*2048];

// ======================= small helpers =======================
__device__ __forceinline__ uint32_t smem_u32(const void* p) {
    uint32_t a;
    asm("{ .reg .u64 t; cvta.to.shared.u64 t, %1; cvt.u32.u64 %0, t; }" : "=r"(a) : "l"(p));
    return a;
}
__device__ __forceinline__ void cp16(uint32_t dst, const float* src, bool v) {
    asm volatile("cp.async.cg.shared.global [%0], [%1], 16, %2;"
                 :: "r"(dst), "l"(src), "r"(v ? 16u : 0u));
}
#define CP_COMMIT() asm volatile("cp.async.commit_group;" ::: "memory")
#define CP_WAIT1()  asm volatile("cp.async.wait_group 1;" ::: "memory")
#define CP_WAIT0()  asm volatile("cp.async.wait_group 0;" ::: "memory")

// ======================= TF32 WMMA GEMM =======================
// C[M, Nvalid] = A[M, K] @ Bt[Nvalid, K]^T. A row-major, Bt row-major.
// CTA 128(M) x 128(N), K-chunk 32, double-buffered cp.async, 256 threads.
// Warp w: wm=(w&1)*64, wn=(w>>1)*32; warp tile 64x32 = 4x2 wmma 16x16x8 frags.
#define TMm 128
#define TNn 128
#define PAD 36
#define STAGE_FLOATS (2 * TMm * PAD)
#define GEMM_SMEM (2 * STAGE_FLOATS * 4)

template<int K>
__global__ __launch_bounds__(256)
void gemm_wmma(const float* __restrict__ A, const float* __restrict__ Bt,
               float* __restrict__ C, int Nvalid, int ldc)
{
    extern __shared__ float sm[];
    float* As[2] = { sm,             sm + STAGE_FLOATS };
    float* Bs[2] = { sm + TMm * PAD, sm + STAGE_FLOATS + TMm * PAD };

    const int tid = threadIdx.x;
    const int wid = tid >> 5;
    const int bm = blockIdx.y * TMm;
    const int bn = blockIdx.x * TNn;

    const int wm = (wid & 1) * 64;
    const int wn = (wid >> 1) * 32;

    // loader mapping: rows (tid>>3)+i*32, 16B chunk (tid&7)
    const int ldr = tid >> 3;
    const int c4 = tid & 7;
    const uint32_t smb = smem_u32(sm);
    const float* pA = A + (size_t)(bm + ldr) * K + c4 * 4;
    const float* pB = Bt + (size_t)(bn + ldr) * K + c4 * 4;

    constexpr int NC = K / 32;

    auto load_chunk = [&](int kn) {
        int s = kn & 1;
        uint32_t ab = smb + (uint32_t)(s * STAGE_FLOATS) * 4;
        uint32_t bb = ab + (uint32_t)(TMm * PAD) * 4;
        const float* a = pA + (size_t)kn * 32;
        const float* b = pB + (size_t)kn * 32;
#pragma unroll
        for (int i = 0; i < 4; i++) {
            int row = ldr + i * 32;
            cp16(ab + (row * PAD + c4 * 4) * 4, a + (size_t)i * 32 * K, true);
            cp16(bb + (row * PAD + c4 * 4) * 4, b + (size_t)i * 32 * K,
                 (bn + row) < Nvalid);   // src-size 0 => zero-fill
        }
        CP_COMMIT();
    };

    wmma::fragment<wmma::accumulator, 16, 16, 8, float> acc[4][2];
#pragma unroll
    for (int mt = 0; mt < 4; mt++)
#pragma unroll
        for (int nt = 0; nt < 2; nt++) wmma::fill_fragment(acc[mt][nt], 0.f);

    load_chunk(0);

    for (int kc = 0; kc < NC; kc++) {
        if (kc + 1 < NC) load_chunk(kc + 1);
        if (kc + 1 < NC) { CP_WAIT1(); } else { CP_WAIT0(); }
        __syncthreads();

        const float* as = As[kc & 1];
        const float* bs = Bs[kc & 1];

#pragma unroll
        for (int k8 = 0; k8 < 4; k8++) {
            const int k0 = k8 * 8;
            wmma::fragment<wmma::matrix_a, 16, 16, 8, wmma::precision::tf32, wmma::row_major> af[4];
            wmma::fragment<wmma::matrix_b, 16, 16, 8, wmma::precision::tf32, wmma::col_major> bf[2];
#pragma unroll
            for (int mt = 0; mt < 4; mt++) {
                wmma::load_matrix_sync(af[mt], as + (wm + mt * 16) * PAD + k0, PAD);
#pragma unroll
                for (int e = 0; e < af[mt].num_elements; e++)
                    af[mt].x[e] = wmma::__float_to_tf32(af[mt].x[e]);
            }
#pragma unroll
            for (int nt = 0; nt < 2; nt++) {
                wmma::load_matrix_sync(bf[nt], bs + (wn + nt * 16) * PAD + k0, PAD);
#pragma unroll
                for (int e = 0; e < bf[nt].num_elements; e++)
                    bf[nt].x[e] = wmma::__float_to_tf32(bf[nt].x[e]);
            }
#pragma unroll
            for (int mt = 0; mt < 4; mt++)
#pragma unroll
                for (int nt = 0; nt < 2; nt++)
                    wmma::mma_sync(acc[mt][nt], af[mt], bf[nt], acc[mt][nt]);
        }
        __syncthreads();
    }

    // epilogue (fragment granularity 16 cols; valid N remainders are multiples of 16)
#pragma unroll
    for (int mt = 0; mt < 4; mt++) {
#pragma unroll
        for (int nt = 0; nt < 2; nt++) {
            int row0 = bm + wm + mt * 16;
            int col0 = bn + wn + nt * 16;
            if (col0 + 16 <= Nvalid)
                wmma::store_matrix_sync(C + (size_t)row0 * ldc + col0, acc[mt][nt],
                                        ldc, wmma::mem_row_major);
        }
    }
}

// ======================= bias add (final projection) =======================
__global__ __launch_bounds__(256)
void bias_add_kernel(float* __restrict__ C, const float* __restrict__ bias)
{
    int row = blockIdx.x;
    int c = threadIdx.x * 4;
    float4 v = *(float4*)(C + (size_t)row * DM + c);
    float4 b = *(const float4*)(bias + c);
    v.x += b.x; v.y += b.y; v.z += b.z; v.w += b.w;
    *(float4*)(C + (size_t)row * DM + c) = v;
}

// ======================= weight transpose =======================
__global__ __launch_bounds__(256)
void transpose_kernel(const float* __restrict__ B, float* __restrict__ Bt, int K, int N)
{
    __shared__ float t[32][33];
    int tx = threadIdx.x, ty = threadIdx.y;
    int n0 = blockIdx.x * 32, k0 = blockIdx.y * 32;
#pragma unroll
    for (int r = 0; r < 4; r++)
        t[ty + r * 8][tx] = B[(size_t)(k0 + ty + r * 8) * N + n0 + tx];
    __syncthreads();
#pragma unroll
    for (int r = 0; r < 4; r++)
        Bt[(size_t)(n0 + ty + r * 8) * K + k0 + tx] = t[tx][ty + r * 8];
}

// ======================= conv + silu + dt softplus/dA =======================
__global__ __launch_bounds__(256)
void conv_silu_kernel(const float* __restrict__ conv_w, const float* __restrict__ conv_b,
                      const float* __restrict__ dt_bias, const float* __restrict__ A_log)
{
    const int idx = blockIdx.x;
    const int t = idx & (Lseq - 1);
    const int b = (idx >> 11) & 3;
    const int d = idx >> 13;

    int ph[4];
#pragma unroll
    for (int k = 0; k < 4; k++) {
        int j = t - 3 + k;
        ph[k] = (j < 0) ? -1 : (d ? (Lseq - 1 - j) : j);
    }

    float* outrow = g_act + ((size_t)(d * Bsz + b) * Lseq + t) * CONVD;

    for (int c = threadIdx.x; c < CONVD; c += 256) {
        float acc = conv_b[c];
#pragma unroll
        for (int k = 0; k < 4; k++) {
            if (ph[k] >= 0) {
                float v = g_zxbcdt[((size_t)b * Lseq + ph[k]) * DIP + DI + c];
                acc += v * conv_w[c * 4 + k];
            }
        }
        outrow[c] = acc / (1.f + expf(-acc));
    }

    if (threadIdx.x < NH) {
        int h = threadIdx.x;
        int pl = d ? (Lseq - 1 - t) : t;
        float raw = g_zxbcdt[((size_t)b * Lseq + pl) * DIP + (DIP - NH) + h] + dt_bias[h];
        float dt = (raw > 20.f) ? raw : log1pf(expf(raw));
        float A = -expf(A_log[h]);
        float dA = expf(dt * A);
        g_dtA[((size_t)(d * Bsz + b) * Lseq + t) * NH + h] = make_float2(dA, dt);
    }
}

// ======================= sequential selective scan =======================
__global__ __launch_bounds__(512)
void scan_kernel(const float* __restrict__ Dvec)
{
    const int h = blockIdx.x & 31;
    const int b = (blockIdx.x >> 5) & 3;
    const int d = blockIdx.x >> 7;

    const int lane = threadIdx.x & 31;
    const int w = threadIdx.x >> 5;
    const int p = w * 4 + (lane >> 3);
    const int n0 = (lane & 7) * 8;

    const float* actb = g_act + (size_t)(d * Bsz + b) * Lseq * CONVD;
    const float2* dtA = g_dtA + (size_t)(d * Bsz + b) * Lseq * NH;
    float* yb = g_y + (size_t)(d * Bsz + b) * Lseq * DI;

    const float Dh = Dvec[h];
    const bool writer = ((lane & 7) == 0);

    float S[8];
#pragma unroll
    for (int j = 0; j < 8; j++) S[j] = 0.f;

    for (int t = 0; t < Lseq; t++) {
        const float* a = actb + (size_t)t * CONVD;
        float4 B0 = *(const float4*)(a + DI + n0);
        float4 B1 = *(const float4*)(a + DI + n0 + 4);
        float4 C0 = *(const float4*)(a + DI + DSTATE + n0);
        float4 C1 = *(const float4*)(a + DI + DSTATE + n0 + 4);
        float xv = a[h * HD + p];
        float2 ad = dtA[t * NH + h];
        float dA = ad.x;
        float dtx = ad.y * xv;

        float y = 0.f;
        S[0] = S[0] * dA + dtx * B0.x; y += S[0] * C0.x;
        S[1] = S[1] * dA + dtx * B0.y; y += S[1] * C0.y;
        S[2] = S[2] * dA + dtx * B0.z; y += S[2] * C0.z;
        S[3] = S[3] * dA + dtx * B0.w; y += S[3] * C0.w;
        S[4] = S[4] * dA + dtx * B1.x; y += S[4] * C1.x;
        S[5] = S[5] * dA + dtx * B1.y; y += S[5] * C1.y;
        S[6] = S[6] * dA + dtx * B1.z; y += S[6] * C1.z;
        S[7] = S[7] * dA + dtx * B1.w; y += S[7] * C1.w;

        y += __shfl_xor_sync(0xFFFFFFFFu, y, 1);
        y += __shfl_xor_sync(0xFFFFFFFFu, y, 2);
        y += __shfl_xor_sync(0xFFFFFFFFu, y, 4);

        if (writer) {
            int pl = d ? (Lseq - 1 - t) : t;
            yb[(size_t)pl * DI + h * HD + p] = y + Dh * xv;
        }
    }
}

// ======================= gate + RMSNorm =======================
__global__ __launch_bounds__(256)
void gate_norm_kernel(const float* __restrict__ norm_w)
{
    const int idx = blockIdx.x;
    const int l = idx & (Lseq - 1);
    const int b = (idx >> 11) & 3;
    const int d = idx >> 13;

    float* yrow = g_y + ((size_t)(d * Bsz + b) * Lseq + l) * DI;
    const float* zrow = g_zxbcdt + ((size_t)b * Lseq + l) * DIP;

    float vals[8];
    float ss = 0.f;
#pragma unroll
    for (int i = 0; i < 8; i++) {
        int c = threadIdx.x + i * 256;
        float yv = yrow[c];
        float z = zrow[c];
        float g = yv * (z / (1.f + expf(-z)));
        vals[i] = g;
        ss += g * g;
    }

    __shared__ float red[8];
#pragma unroll
    for (int m = 16; m > 0; m >>= 1) ss += __shfl_xor_sync(0xFFFFFFFFu, ss, m);
    if ((threadIdx.x & 31) == 0) red[threadIdx.x >> 5] = ss;
    __syncthreads();
    if (threadIdx.x < 8) {
        float v = red[threadIdx.x];
#pragma unroll
        for (int m = 4; m > 0; m >>= 1) v += __shfl_xor_sync(0xFFu, v, m);
        if (threadIdx.x == 0) red[0] = v;
    }
    __syncthreads();
    float scale = rsqrtf(red[0] * (1.f / DI) + 1e-5f);

#pragma unroll
    for (int i = 0; i < 8; i++) {
        int c = threadIdx.x + i * 256;
        yrow[c] = vals[i] * scale * norm_w[c];
    }
}

// ======================= launch =======================
extern "C" void kernel_launch(void* const* d_in, const int* in_sizes, int n_in,
                              void* d_out, int out_size)
{
    const float* x          = (const float*)d_in[0];
    const float* in_proj_w  = (const float*)d_in[1];
    const float* conv_w     = (const float*)d_in[2];
    const float* conv_b     = (const float*)d_in[3];
    const float* dt_bias    = (const float*)d_in[4];
    const float* A_log      = (const float*)d_in[5];
    const float* Dvec       = (const float*)d_in[6];
    const float* norm_w     = (const float*)d_in[7];
    const float* out_proj_w = (const float*)d_in[8];
    const float* proj_w     = (const float*)d_in[9];
    const float* proj_b     = (const float*)d_in[10];
    float* out = (float*)d_out;

    float* zp;  cudaGetSymbolAddress((void**)&zp, g_zxbcdt);
    float* yp;  cudaGetSymbolAddress((void**)&yp, g_y);
    float* cp;  cudaGetSymbolAddress((void**)&cp, g_cat);
    float* wT;  cudaGetSymbolAddress((void**)&wT, g_wT);

    float* inT   = wT;                          // [4256,1024]
    float* outT  = wT + 4256 * 1024;            // [1024,2048]
    float* projT = outT + 1024 * 2048;          // [1024,2048]

    cudaFuncSetAttribute(gemm_wmma<1024>, cudaFuncAttributeMaxDynamicSharedMemorySize, GEMM_SMEM);
    cudaFuncSetAttribute(gemm_wmma<2048>, cudaFuncAttributeMaxDynamicSharedMemorySize, GEMM_SMEM);

    dim3 tb(32, 8);
    transpose_kernel<<<dim3(DIP / 32, DM / 32), tb>>>(in_proj_w, inT, DM, DIP);
    transpose_kernel<<<dim3(DM / 32, DI / 32), tb>>>(out_proj_w, outT, DI, DM);
    transpose_kernel<<<dim3(DM / 32, DI / 32), tb>>>(proj_w, projT, 2 * DM, DM);

    // 1) in_proj: zxbcdt[8192,4256] = x[8192,1024] @ inT^T
    gemm_wmma<1024><<<dim3((DIP + TNn - 1) / TNn, NTOK / TMm), 256, GEMM_SMEM>>>(
        x, inT, zp, DIP, DIP);

    // 2) conv + silu + dt prep
    conv_silu_kernel<<<2 * NTOK, 256>>>(conv_w, conv_b, dt_bias, A_log);

    // 3) selective scan
    scan_kernel<<<2 * Bsz * NH, 512>>>(Dvec);

    // 4) gate + RMSNorm
    gate_norm_kernel<<<2 * NTOK, 256>>>(norm_w);

    // 5) out_proj per direction into concat buffer
    gemm_wmma<2048><<<dim3(DM / TNn, NTOK / TMm), 256, GEMM_SMEM>>>(
        yp, outT, cp, DM, 2 * DM);
    gemm_wmma<2048><<<dim3(DM / TNn, NTOK / TMm), 256, GEMM_SMEM>>>(
        yp + (size_t)NTOK * DI, outT, cp + DM, DM, 2 * DM);

    // 6) final projection, then bias add
    gemm_wmma<2048><<<dim3(DM / TNn, NTOK / TMm), 256, GEMM_SMEM>>>(
        cp, projT, out, DM, DM);
    bias_add_kernel<<<NTOK, 256>>>(out, proj_b);
}

// round 7
// speedup vs baseline: 1.3197x; 1.0906x over previous
#include <cuda_runtime.h>
#include <cuda_bf16.h>
#include <mma.h>
#include <cstdint>
#include <math.h>

using namespace nvcuda;

// ---------------- problem constants ----------------
#define Bsz 4
#define Lseq 2048
#define DM 1024
#define DSTATE 64
#define DI 2048          // D_INNER
#define NH 32            // NHEADS
#define HD 64            // HEADDIM
#define CONVD 2176       // CONV_DIM
#define DIP 4256         // D_IN_PROJ
#define NTOK (Bsz*Lseq)  // 8192

// ---------------- scratch (static device memory; no allocations) ----------------
__device__ float g_zxbcdt[(size_t)NTOK * DIP];
__device__ float g_act[2ull * NTOK * CONVD];
__device__ float2 g_dtA[2ull * NTOK * NH];
__device__ float g_y[2ull * NTOK * DI];
__device__ float g_cat[(size_t)NTOK * (2*DM)];
__device__ float g_xr[(size_t)NTOK * DM];      // tf32-rounded x
// transposed+rounded weights: inT[4256,1024], outT[1024,2048], projT[1024,2048]
__device__ float g_wT[4256*1024 + 1024*2048 + 1024*2048];

// ======================= small helpers =======================
__device__ __forceinline__ uint32_t smem_u32(const void* p) {
    uint32_t a;
    asm("{ .reg .u64 t; cvta.to.shared.u64 t, %1; cvt.u32.u64 %0, t; }" : "=r"(a) : "l"(p));
    return a;
}
__device__ __forceinline__ void cp16(uint32_t dst, const float* src, bool v) {
    asm volatile("cp.async.cg.shared.global [%0], [%1], 16, %2;"
                 :: "r"(dst), "l"(src), "r"(v ? 16u : 0u));
}
#define CP_COMMIT() asm volatile("cp.async.commit_group;" ::: "memory")
#define CP_WAIT1()  asm volatile("cp.async.wait_group 1;" ::: "memory")
#define CP_WAIT0()  asm volatile("cp.async.wait_group 0;" ::: "memory")

__device__ __forceinline__ float roundtf(float v) {
    uint32_t u;
    asm("cvt.rna.tf32.f32 %0, %1;" : "=r"(u) : "f"(v));
    return __uint_as_float(u);
}

// ======================= TF32 WMMA GEMM (inputs pre-rounded to tf32) =======================
// C[M, Nvalid] = A[M, K] @ Bt[Nvalid, K]^T. A row-major, Bt row-major.
// CTA 128(M) x 128(N), K-chunk 32, double-buffered cp.async, 256 threads, 2 CTAs/SM.
#define TMm 128
#define TNn 128
#define PAD 36
#define STAGE_FLOATS (2 * TMm * PAD)
#define GEMM_SMEM (2 * STAGE_FLOATS * 4)

template<int K, bool ROUND>
__global__ __launch_bounds__(256, 2)
void gemm_wmma(const float* __restrict__ A, const float* __restrict__ Bt,
               float* __restrict__ C, int Nvalid, int ldc)
{
    extern __shared__ float sm[];
    float* As[2] = { sm,             sm + STAGE_FLOATS };
    float* Bs[2] = { sm + TMm * PAD, sm + STAGE_FLOATS + TMm * PAD };

    const int tid = threadIdx.x;
    const int wid = tid >> 5;
    const int bm = blockIdx.y * TMm;
    const int bn = blockIdx.x * TNn;

    const int wm = (wid & 1) * 64;
    const int wn = (wid >> 1) * 32;

    const int ldr = tid >> 3;
    const int c4 = tid & 7;
    const uint32_t smb = smem_u32(sm);
    const float* pA = A + (size_t)(bm + ldr) * K + c4 * 4;
    const float* pB = Bt + (size_t)(bn + ldr) * K + c4 * 4;

    constexpr int NC = K / 32;

    auto load_chunk = [&](int kn) {
        int s = kn & 1;
        uint32_t ab = smb + (uint32_t)(s * STAGE_FLOATS) * 4;
        uint32_t bb = ab + (uint32_t)(TMm * PAD) * 4;
        const float* a = pA + (size_t)kn * 32;
        const float* b = pB + (size_t)kn * 32;
#pragma unroll
        for (int i = 0; i < 4; i++) {
            int row = ldr + i * 32;
            cp16(ab + (row * PAD + c4 * 4) * 4, a + (size_t)i * 32 * K, true);
            cp16(bb + (row * PAD + c4 * 4) * 4, b + (size_t)i * 32 * K,
                 (bn + row) < Nvalid);   // src-size 0 => zero-fill
        }
        CP_COMMIT();
    };

    wmma::fragment<wmma::accumulator, 16, 16, 8, float> acc[4][2];
#pragma unroll
    for (int mt = 0; mt < 4; mt++)
#pragma unroll
        for (int nt = 0; nt < 2; nt++) wmma::fill_fragment(acc[mt][nt], 0.f);

    load_chunk(0);

    for (int kc = 0; kc < NC; kc++) {
        if (kc + 1 < NC) load_chunk(kc + 1);
        if (kc + 1 < NC) { CP_WAIT1(); } else { CP_WAIT0(); }
        __syncthreads();

        const float* as = As[kc & 1];
        const float* bs = Bs[kc & 1];

#pragma unroll
        for (int k8 = 0; k8 < 4; k8++) {
            const int k0 = k8 * 8;
            wmma::fragment<wmma::matrix_a, 16, 16, 8, wmma::precision::tf32, wmma::row_major> af[4];
            wmma::fragment<wmma::matrix_b, 16, 16, 8, wmma::precision::tf32, wmma::col_major> bf[2];
#pragma unroll
            for (int mt = 0; mt < 4; mt++)
                wmma::load_matrix_sync(af[mt], as + (wm + mt * 16) * PAD + k0, PAD);
#pragma unroll
            for (int nt = 0; nt < 2; nt++)
                wmma::load_matrix_sync(bf[nt], bs + (wn + nt * 16) * PAD + k0, PAD);
#pragma unroll
            for (int mt = 0; mt < 4; mt++)
#pragma unroll
                for (int nt = 0; nt < 2; nt++)
                    wmma::mma_sync(acc[mt][nt], af[mt], bf[nt], acc[mt][nt]);
        }
        __syncthreads();
    }

    // epilogue (N remainders are multiples of 16 for our shapes)
#pragma unroll
    for (int mt = 0; mt < 4; mt++) {
#pragma unroll
        for (int nt = 0; nt < 2; nt++) {
            int row0 = bm + wm + mt * 16;
            int col0 = bn + wn + nt * 16;
            if (col0 + 16 <= Nvalid) {
                if (ROUND) {
#pragma unroll
                    for (int e = 0; e < acc[mt][nt].num_elements; e++)
                        acc[mt][nt].x[e] = roundtf(acc[mt][nt].x[e]);
                }
                wmma::store_matrix_sync(C + (size_t)row0 * ldc + col0, acc[mt][nt],
                                        ldc, wmma::mem_row_major);
            }
        }
    }
}

// ======================= bias add (final projection) =======================
__global__ __launch_bounds__(256)
void bias_add_kernel(float* __restrict__ C, const float* __restrict__ bias)
{
    int row = blockIdx.x;
    int c = threadIdx.x * 4;
    float4 v = *(float4*)(C + (size_t)row * DM + c);
    float4 b = *(const float4*)(bias + c);
    v.x += b.x; v.y += b.y; v.z += b.z; v.w += b.w;
    *(float4*)(C + (size_t)row * DM + c) = v;
}

// ======================= round x to tf32 =======================
__global__ __launch_bounds__(256)
void round_kernel(const float* __restrict__ in, float* __restrict__ out)
{
    size_t i = ((size_t)blockIdx.x * 256 + threadIdx.x) * 4;
    float4 v = *(const float4*)(in + i);
    v.x = roundtf(v.x); v.y = roundtf(v.y); v.z = roundtf(v.z); v.w = roundtf(v.w);
    *(float4*)(out + i) = v;
}

// ======================= weight transpose (+tf32 round) =======================
__global__ __launch_bounds__(256)
void transpose_kernel(const float* __restrict__ B, float* __restrict__ Bt, int K, int N)
{
    __shared__ float t[32][33];
    int tx = threadIdx.x, ty = threadIdx.y;
    int n0 = blockIdx.x * 32, k0 = blockIdx.y * 32;
#pragma unroll
    for (int r = 0; r < 4; r++)
        t[ty + r * 8][tx] = B[(size_t)(k0 + ty + r * 8) * N + n0 + tx];
    __syncthreads();
#pragma unroll
    for (int r = 0; r < 4; r++)
        Bt[(size_t)(n0 + ty + r * 8) * K + k0 + tx] = roundtf(t[tx][ty + r * 8]);
}

// ======================= conv + silu + dt softplus/dA (8 timesteps per CTA) =======================
// grid: 2*Bsz*(Lseq/8). Block handles (d, b, t0..t0+7) in LOGICAL time.
__global__ __launch_bounds__(256)
void conv_silu_kernel(const float* __restrict__ conv_w, const float* __restrict__ conv_b,
                      const float* __restrict__ dt_bias, const float* __restrict__ A_log)
{
    const int seg = blockIdx.x;
    const int t0 = (seg & (Lseq / 8 - 1)) * 8;
    const int b = (seg >> 8) & 3;
    const int d = seg >> 10;

    float* outbase = g_act + ((size_t)(d * Bsz + b) * Lseq + t0) * CONVD;

    for (int c = threadIdx.x; c < CONVD; c += 256) {
        float w0 = conv_w[c * 4 + 0], w1 = conv_w[c * 4 + 1];
        float w2 = conv_w[c * 4 + 2], w3 = conv_w[c * 4 + 3];
        float cb = conv_b[c];
        float taps[11];
#pragma unroll
        for (int j = 0; j < 11; j++) {
            int lt = t0 - 3 + j;
            if (lt < 0) { taps[j] = 0.f; }
            else {
                int pl = d ? (Lseq - 1 - lt) : lt;
                taps[j] = g_zxbcdt[((size_t)b * Lseq + pl) * DIP + DI + c];
            }
        }
#pragma unroll
        for (int k = 0; k < 8; k++) {
            float acc = cb + taps[k] * w0 + taps[k + 1] * w1
                           + taps[k + 2] * w2 + taps[k + 3] * w3;
            outbase[(size_t)k * CONVD + c] = acc / (1.f + expf(-acc));
        }
    }

    // dt: thread tid -> (k = tid>>5, h = tid&31)
    {
        int k = threadIdx.x >> 5;
        int h = threadIdx.x & 31;
        int t = t0 + k;
        int pl = d ? (Lseq - 1 - t) : t;
        float raw = g_zxbcdt[((size_t)b * Lseq + pl) * DIP + (DIP - NH) + h] + dt_bias[h];
        float dt = (raw > 20.f) ? raw : log1pf(expf(raw));
        float A = -expf(A_log[h]);
        float dA = expf(dt * A);
        g_dtA[((size_t)(d * Bsz + b) * Lseq + t) * NH + h] = make_float2(dA, dt);
    }
}

// ======================= sequential selective scan (with prefetch) =======================
__global__ __launch_bounds__(512)
void scan_kernel(const float* __restrict__ Dvec)
{
    const int h = blockIdx.x & 31;
    const int b = (blockIdx.x >> 5) & 3;
    const int d = blockIdx.x >> 7;

    const int lane = threadIdx.x & 31;
    const int w = threadIdx.x >> 5;
    const int p = w * 4 + (lane >> 3);
    const int n0 = (lane & 7) * 8;

    const float* actb = g_act + (size_t)(d * Bsz + b) * Lseq * CONVD;
    const float2* dtA = g_dtA + (size_t)(d * Bsz + b) * Lseq * NH;
    float* yb = g_y + (size_t)(d * Bsz + b) * Lseq * DI;

    const float Dh = Dvec[h];
    const bool writer = ((lane & 7) == 0);

    float S[8];
#pragma unroll
    for (int j = 0; j < 8; j++) S[j] = 0.f;

    // prefetch registers
    float4 nB0, nB1, nC0, nC1;
    float nxv;
    float2 nad;
    {
        const float* a = actb;
        nB0 = *(const float4*)(a + DI + n0);
        nB1 = *(const float4*)(a + DI + n0 + 4);
        nC0 = *(const float4*)(a + DI + DSTATE + n0);
        nC1 = *(const float4*)(a + DI + DSTATE + n0 + 4);
        nxv = a[h * HD + p];
        nad = dtA[h];
    }

    for (int t = 0; t < Lseq; t++) {
        float4 B0 = nB0, B1 = nB1, C0 = nC0, C1 = nC1;
        float xv = nxv;
        float2 ad = nad;

        if (t + 1 < Lseq) {
            const float* a = actb + (size_t)(t + 1) * CONVD;
            nB0 = *(const float4*)(a + DI + n0);
            nB1 = *(const float4*)(a + DI + n0 + 4);
            nC0 = *(const float4*)(a + DI + DSTATE + n0);
            nC1 = *(const float4*)(a + DI + DSTATE + n0 + 4);
            nxv = a[h * HD + p];
            nad = dtA[(size_t)(t + 1) * NH + h];
        }

        float dA = ad.x;
        float dtx = ad.y * xv;

        float y = 0.f;
        S[0] = S[0] * dA + dtx * B0.x; y += S[0] * C0.x;
        S[1] = S[1] * dA + dtx * B0.y; y += S[1] * C0.y;
        S[2] = S[2] * dA + dtx * B0.z; y += S[2] * C0.z;
        S[3] = S[3] * dA + dtx * B0.w; y += S[3] * C0.w;
        S[4] = S[4] * dA + dtx * B1.x; y += S[4] * C1.x;
        S[5] = S[5] * dA + dtx * B1.y; y += S[5] * C1.y;
        S[6] = S[6] * dA + dtx * B1.z; y += S[6] * C1.z;
        S[7] = S[7] * dA + dtx * B1.w; y += S[7] * C1.w;

        y += __shfl_xor_sync(0xFFFFFFFFu, y, 1);
        y += __shfl_xor_sync(0xFFFFFFFFu, y, 2);
        y += __shfl_xor_sync(0xFFFFFFFFu, y, 4);

        if (writer) {
            int pl = d ? (Lseq - 1 - t) : t;
            yb[(size_t)pl * DI + h * HD + p] = y + Dh * xv;
        }
    }
}

// ======================= gate + RMSNorm (+tf32 round of y) =======================
__global__ __launch_bounds__(256)
void gate_norm_kernel(const float* __restrict__ norm_w)
{
    const int idx = blockIdx.x;
    const int l = idx & (Lseq - 1);
    const int b = (idx >> 11) & 3;
    const int d = idx >> 13;

    float* yrow = g_y + ((size_t)(d * Bsz + b) * Lseq + l) * DI;
    const float* zrow = g_zxbcdt + ((size_t)b * Lseq + l) * DIP;

    float vals[8];
    float ss = 0.f;
#pragma unroll
    for (int i = 0; i < 8; i++) {
        int c = threadIdx.x + i * 256;
        float yv = yrow[c];
        float z = zrow[c];
        float g = yv * (z / (1.f + expf(-z)));
        vals[i] = g;
        ss += g * g;
    }

    __shared__ float red[8];
#pragma unroll
    for (int m = 16; m > 0; m >>= 1) ss += __shfl_xor_sync(0xFFFFFFFFu, ss, m);
    if ((threadIdx.x & 31) == 0) red[threadIdx.x >> 5] = ss;
    __syncthreads();
    if (threadIdx.x < 8) {
        float v = red[threadIdx.x];
#pragma unroll
        for (int m = 4; m > 0; m >>= 1) v += __shfl_xor_sync(0xFFu, v, m);
        if (threadIdx.x == 0) red[0] = v;
    }
    __syncthreads();
    float scale = rsqrtf(red[0] * (1.f / DI) + 1e-5f);

#pragma unroll
    for (int i = 0; i < 8; i++) {
        int c = threadIdx.x + i * 256;
        yrow[c] = roundtf(vals[i] * scale * norm_w[c]);
    }
}

// ======================= launch =======================
extern "C" void kernel_launch(void* const* d_in, const int* in_sizes, int n_in,
                              void* d_out, int out_size)
{
    const float* x          = (const float*)d_in[0];
    const float* in_proj_w  = (const float*)d_in[1];
    const float* conv_w     = (const float*)d_in[2];
    const float* conv_b     = (const float*)d_in[3];
    const float* dt_bias    = (const float*)d_in[4];
    const float* A_log      = (const float*)d_in[5];
    const float* Dvec       = (const float*)d_in[6];
    const float* norm_w     = (const float*)d_in[7];
    const float* out_proj_w = (const float*)d_in[8];
    const float* proj_w     = (const float*)d_in[9];
    const float* proj_b     = (const float*)d_in[10];
    float* out = (float*)d_out;

    float* zp;  cudaGetSymbolAddress((void**)&zp, g_zxbcdt);
    float* yp;  cudaGetSymbolAddress((void**)&yp, g_y);
    float* cp;  cudaGetSymbolAddress((void**)&cp, g_cat);
    float* xr;  cudaGetSymbolAddress((void**)&xr, g_xr);
    float* wT;  cudaGetSymbolAddress((void**)&wT, g_wT);

    float* inT   = wT;                          // [4256,1024]
    float* outT  = wT + 4256 * 1024;            // [1024,2048]
    float* projT = outT + 1024 * 2048;          // [1024,2048]

    cudaFuncSetAttribute(gemm_wmma<1024, false>, cudaFuncAttributeMaxDynamicSharedMemorySize, GEMM_SMEM);
    cudaFuncSetAttribute(gemm_wmma<2048, false>, cudaFuncAttributeMaxDynamicSharedMemorySize, GEMM_SMEM);
    cudaFuncSetAttribute(gemm_wmma<2048, true>,  cudaFuncAttributeMaxDynamicSharedMemorySize, GEMM_SMEM);

    dim3 tb(32, 8);
    transpose_kernel<<<dim3(DIP / 32, DM / 32), tb>>>(in_proj_w, inT, DM, DIP);
    transpose_kernel<<<dim3(DM / 32, DI / 32), tb>>>(out_proj_w, outT, DI, DM);
    transpose_kernel<<<dim3(DM / 32, DI / 32), tb>>>(proj_w, projT, 2 * DM, DM);
    round_kernel<<<(NTOK * DM) / 1024, 256>>>(x, xr);

    // 1) in_proj: zxbcdt[8192,4256] = xr @ inT^T
    gemm_wmma<1024, false><<<dim3((DIP + TNn - 1) / TNn, NTOK / TMm), 256, GEMM_SMEM>>>(
        xr, inT, zp, DIP, DIP);

    // 2) conv + silu + dt prep (8 timesteps per CTA)
    conv_silu_kernel<<<2 * Bsz * (Lseq / 8), 256>>>(conv_w, conv_b, dt_bias, A_log);

    // 3) selective scan
    scan_kernel<<<2 * Bsz * NH, 512>>>(Dvec);

    // 4) gate + RMSNorm (writes tf32-rounded y)
    gate_norm_kernel<<<2 * NTOK, 256>>>(norm_w);

    // 5) out_proj per direction into concat buffer (rounded for final GEMM)
    gemm_wmma<2048, true><<<dim3(DM / TNn, NTOK / TMm), 256, GEMM_SMEM>>>(
        yp, outT, cp, DM, 2 * DM);
    gemm_wmma<2048, true><<<dim3(DM / TNn, NTOK / TMm), 256, GEMM_SMEM>>>(
        yp + (size_t)NTOK * DI, outT, cp + DM, DM, 2 * DM);

    // 6) final projection, then bias add
    gemm_wmma<2048, false><<<dim3(DM / TNn, NTOK / TMm), 256, GEMM_SMEM>>>(
        cp, projT, out, DM, DM);
    bias_add_kernel<<<NTOK, 256>>>(out, proj_b);
}

// round 8
// speedup vs baseline: 1.4267x; 1.0811x over previous
#include <cuda_runtime.h>
#include <cuda_bf16.h>
#include <mma.h>
#include <cstdint>
#include <math.h>

using namespace nvcuda;

// ---------------- problem constants ----------------
#define Bsz 4
#define Lseq 2048
#define DM 1024
#define DSTATE 64
#define DI 2048          // D_INNER
#define NH 32            // NHEADS
#define HD 64            // HEADDIM
#define CONVD 2176       // CONV_DIM
#define DIP 4256         // D_IN_PROJ
#define NTOK (Bsz*Lseq)  // 8192

// ---------------- scratch (static device memory; no allocations) ----------------
__device__ float g_zxbcdt[(size_t)NTOK * DIP];
__device__ float g_act[2ull * NTOK * CONVD];
__device__ float2 g_dtA[2ull * NTOK * NH];
__device__ float g_y[2ull * NTOK * DI];
__device__ float g_cat[(size_t)NTOK * (2*DM)];
__device__ float g_xr[(size_t)NTOK * DM];      // tf32-rounded x
// transposed+rounded weights: inT[4256,1024], outT[1024,2048], projT[1024,2048]
__device__ float g_wT[4256*1024 + 1024*2048 + 1024*2048];

// ======================= small helpers =======================
__device__ __forceinline__ uint32_t smem_u32(const void* p) {
    uint32_t a;
    asm("{ .reg .u64 t; cvta.to.shared.u64 t, %1; cvt.u32.u64 %0, t; }" : "=r"(a) : "l"(p));
    return a;
}
__device__ __forceinline__ void cp16(uint32_t dst, const float* src, bool v) {
    asm volatile("cp.async.cg.shared.global [%0], [%1], 16, %2;"
                 :: "r"(dst), "l"(src), "r"(v ? 16u : 0u));
}
#define CP_COMMIT() asm volatile("cp.async.commit_group;" ::: "memory")
#define CP_WAIT1()  asm volatile("cp.async.wait_group 1;" ::: "memory")
#define CP_WAIT0()  asm volatile("cp.async.wait_group 0;" ::: "memory")

__device__ __forceinline__ float roundtf(float v) {
    uint32_t u;
    asm("cvt.rna.tf32.f32 %0, %1;" : "=r"(u) : "f"(v));
    return __uint_as_float(u);
}

// ======================= TF32 WMMA GEMM (inputs pre-rounded to tf32) =======================
// C[M, Nvalid] = A[M, K] @ Bt[Nvalid, K]^T. A row-major, Bt row-major.
// CTA tile 128(M) x 256(N), 8 warps (2M x 4N), warp tile 64x64.
// K-chunk 32, double-buffered cp.async, 256 threads, 1 CTA/SM.
#define TMm 128
#define TNn 256
#define PAD 36
#define A_FLOATS (TMm * PAD)                 // 4608
#define B_FLOATS (TNn * PAD)                 // 9216
#define STAGE_FLOATS (A_FLOATS + B_FLOATS)   // 13824
#define GEMM_SMEM (2 * STAGE_FLOATS * 4)     // 110592 B

template<int K, bool ROUND>
__global__ __launch_bounds__(256)
void gemm_wmma(const float* __restrict__ A, const float* __restrict__ Bt,
               float* __restrict__ C, int Nvalid, int ldc)
{
    extern __shared__ float sm[];
    float* As[2] = { sm,            sm + STAGE_FLOATS };
    float* Bs[2] = { sm + A_FLOATS, sm + STAGE_FLOATS + A_FLOATS };

    const int tid = threadIdx.x;
    const int wid = tid >> 5;
    const int bm = blockIdx.y * TMm;
    const int bn = blockIdx.x * TNn;

    const int wm = (wid & 1) * 64;       // 2 warps in M
    const int wn = (wid >> 1) * 64;      // 4 warps in N

    // loader mapping: rows tr + i*32, 16B chunk c4 within 128B (32-float) row
    const int tr = tid >> 3;
    const int c4 = tid & 7;
    const uint32_t smb = smem_u32(sm);
    const float* pA = A + (size_t)(bm + tr) * K + c4 * 4;
    const float* pB = Bt + (size_t)(bn + tr) * K + c4 * 4;

    constexpr int NC = K / 32;

    auto load_chunk = [&](int kn) {
        int s = kn & 1;
        uint32_t ab = smb + (uint32_t)(s * STAGE_FLOATS) * 4;
        uint32_t bb = ab + (uint32_t)A_FLOATS * 4;
        const float* a = pA + (size_t)kn * 32;
        const float* b = pB + (size_t)kn * 32;
#pragma unroll
        for (int i = 0; i < 4; i++) {
            int row = tr + i * 32;
            cp16(ab + (row * PAD + c4 * 4) * 4, a + (size_t)i * 32 * K, true);
        }
#pragma unroll
        for (int i = 0; i < 8; i++) {
            int row = tr + i * 32;
            cp16(bb + (row * PAD + c4 * 4) * 4, b + (size_t)i * 32 * K,
                 (bn + row) < Nvalid);   // src-size 0 => zero-fill
        }
        CP_COMMIT();
    };

    wmma::fragment<wmma::accumulator, 16, 16, 8, float> acc[4][4];
#pragma unroll
    for (int mt = 0; mt < 4; mt++)
#pragma unroll
        for (int nt = 0; nt < 4; nt++) wmma::fill_fragment(acc[mt][nt], 0.f);

    load_chunk(0);

    for (int kc = 0; kc < NC; kc++) {
        if (kc + 1 < NC) load_chunk(kc + 1);
        if (kc + 1 < NC) { CP_WAIT1(); } else { CP_WAIT0(); }
        __syncthreads();

        const float* as = As[kc & 1];
        const float* bs = Bs[kc & 1];

#pragma unroll
        for (int k8 = 0; k8 < 4; k8++) {
            const int k0 = k8 * 8;
            wmma::fragment<wmma::matrix_a, 16, 16, 8, wmma::precision::tf32, wmma::row_major> af[4];
            wmma::fragment<wmma::matrix_b, 16, 16, 8, wmma::precision::tf32, wmma::col_major> bf[4];
#pragma unroll
            for (int mt = 0; mt < 4; mt++)
                wmma::load_matrix_sync(af[mt], as + (wm + mt * 16) * PAD + k0, PAD);
#pragma unroll
            for (int nt = 0; nt < 4; nt++)
                wmma::load_matrix_sync(bf[nt], bs + (wn + nt * 16) * PAD + k0, PAD);
#pragma unroll
            for (int mt = 0; mt < 4; mt++)
#pragma unroll
                for (int nt = 0; nt < 4; nt++)
                    wmma::mma_sync(acc[mt][nt], af[mt], bf[nt], acc[mt][nt]);
        }
        __syncthreads();
    }

    // epilogue (N remainders are multiples of 16 for our shapes)
#pragma unroll
    for (int mt = 0; mt < 4; mt++) {
#pragma unroll
        for (int nt = 0; nt < 4; nt++) {
            int row0 = bm + wm + mt * 16;
            int col0 = bn + wn + nt * 16;
            if (col0 + 16 <= Nvalid) {
                if (ROUND) {
#pragma unroll
                    for (int e = 0; e < acc[mt][nt].num_elements; e++)
                        acc[mt][nt].x[e] = roundtf(acc[mt][nt].x[e]);
                }
                wmma::store_matrix_sync(C + (size_t)row0 * ldc + col0, acc[mt][nt],
                                        ldc, wmma::mem_row_major);
            }
        }
    }
}

// ======================= bias add (final projection) =======================
__global__ __launch_bounds__(256)
void bias_add_kernel(float* __restrict__ C, const float* __restrict__ bias)
{
    int row = blockIdx.x;
    int c = threadIdx.x * 4;
    float4 v = *(float4*)(C + (size_t)row * DM + c);
    float4 b = *(const float4*)(bias + c);
    v.x += b.x; v.y += b.y; v.z += b.z; v.w += b.w;
    *(float4*)(C + (size_t)row * DM + c) = v;
}

// ======================= round x to tf32 =======================
__global__ __launch_bounds__(256)
void round_kernel(const float* __restrict__ in, float* __restrict__ out)
{
    size_t i = ((size_t)blockIdx.x * 256 + threadIdx.x) * 4;
    float4 v = *(const float4*)(in + i);
    v.x = roundtf(v.x); v.y = roundtf(v.y); v.z = roundtf(v.z); v.w = roundtf(v.w);
    *(float4*)(out + i) = v;
}

// ======================= weight transpose (+tf32 round) =======================
__global__ __launch_bounds__(256)
void transpose_kernel(const float* __restrict__ B, float* __restrict__ Bt, int K, int N)
{
    __shared__ float t[32][33];
    int tx = threadIdx.x, ty = threadIdx.y;
    int n0 = blockIdx.x * 32, k0 = blockIdx.y * 32;
#pragma unroll
    for (int r = 0; r < 4; r++)
        t[ty + r * 8][tx] = B[(size_t)(k0 + ty + r * 8) * N + n0 + tx];
    __syncthreads();
#pragma unroll
    for (int r = 0; r < 4; r++)
        Bt[(size_t)(n0 + ty + r * 8) * K + k0 + tx] = roundtf(t[tx][ty + r * 8]);
}

// ======================= conv + silu + dt softplus/dA (8 timesteps per CTA) =======================
__global__ __launch_bounds__(256)
void conv_silu_kernel(const float* __restrict__ conv_w, const float* __restrict__ conv_b,
                      const float* __restrict__ dt_bias, const float* __restrict__ A_log)
{
    const int seg = blockIdx.x;
    const int t0 = (seg & (Lseq / 8 - 1)) * 8;
    const int b = (seg >> 8) & 3;
    const int d = seg >> 10;

    float* outbase = g_act + ((size_t)(d * Bsz + b) * Lseq + t0) * CONVD;

    for (int c = threadIdx.x; c < CONVD; c += 256) {
        float w0 = conv_w[c * 4 + 0], w1 = conv_w[c * 4 + 1];
        float w2 = conv_w[c * 4 + 2], w3 = conv_w[c * 4 + 3];
        float cb = conv_b[c];
        float taps[11];
#pragma unroll
        for (int j = 0; j < 11; j++) {
            int lt = t0 - 3 + j;
            if (lt < 0) { taps[j] = 0.f; }
            else {
                int pl = d ? (Lseq - 1 - lt) : lt;
                taps[j] = g_zxbcdt[((size_t)b * Lseq + pl) * DIP + DI + c];
            }
        }
#pragma unroll
        for (int k = 0; k < 8; k++) {
            float acc = cb + taps[k] * w0 + taps[k + 1] * w1
                           + taps[k + 2] * w2 + taps[k + 3] * w3;
            outbase[(size_t)k * CONVD + c] = acc / (1.f + expf(-acc));
        }
    }

    {
        int k = threadIdx.x >> 5;
        int h = threadIdx.x & 31;
        int t = t0 + k;
        int pl = d ? (Lseq - 1 - t) : t;
        float raw = g_zxbcdt[((size_t)b * Lseq + pl) * DIP + (DIP - NH) + h] + dt_bias[h];
        float dt = (raw > 20.f) ? raw : log1pf(expf(raw));
        float A = -expf(A_log[h]);
        float dA = expf(dt * A);
        g_dtA[((size_t)(d * Bsz + b) * Lseq + t) * NH + h] = make_float2(dA, dt);
    }
}

// ======================= sequential selective scan (with prefetch) =======================
__global__ __launch_bounds__(512)
void scan_kernel(const float* __restrict__ Dvec)
{
    const int h = blockIdx.x & 31;
    const int b = (blockIdx.x >> 5) & 3;
    const int d = blockIdx.x >> 7;

    const int lane = threadIdx.x & 31;
    const int w = threadIdx.x >> 5;
    const int p = w * 4 + (lane >> 3);
    const int n0 = (lane & 7) * 8;

    const float* actb = g_act + (size_t)(d * Bsz + b) * Lseq * CONVD;
    const float2* dtA = g_dtA + (size_t)(d * Bsz + b) * Lseq * NH;
    float* yb = g_y + (size_t)(d * Bsz + b) * Lseq * DI;

    const float Dh = Dvec[h];
    const bool writer = ((lane & 7) == 0);

    float S[8];
#pragma unroll
    for (int j = 0; j < 8; j++) S[j] = 0.f;

    float4 nB0, nB1, nC0, nC1;
    float nxv;
    float2 nad;
    {
        const float* a = actb;
        nB0 = *(const float4*)(a + DI + n0);
        nB1 = *(const float4*)(a + DI + n0 + 4);
        nC0 = *(const float4*)(a + DI + DSTATE + n0);
        nC1 = *(const float4*)(a + DI + DSTATE + n0 + 4);
        nxv = a[h * HD + p];
        nad = dtA[h];
    }

    for (int t = 0; t < Lseq; t++) {
        float4 B0 = nB0, B1 = nB1, C0 = nC0, C1 = nC1;
        float xv = nxv;
        float2 ad = nad;

        if (t + 1 < Lseq) {
            const float* a = actb + (size_t)(t + 1) * CONVD;
            nB0 = *(const float4*)(a + DI + n0);
            nB1 = *(const float4*)(a + DI + n0 + 4);
            nC0 = *(const float4*)(a + DI + DSTATE + n0);
            nC1 = *(const float4*)(a + DI + DSTATE + n0 + 4);
            nxv = a[h * HD + p];
            nad = dtA[(size_t)(t + 1) * NH + h];
        }

        float dA = ad.x;
        float dtx = ad.y * xv;

        float y = 0.f;
        S[0] = S[0] * dA + dtx * B0.x; y += S[0] * C0.x;
        S[1] = S[1] * dA + dtx * B0.y; y += S[1] * C0.y;
        S[2] = S[2] * dA + dtx * B0.z; y += S[2] * C0.z;
        S[3] = S[3] * dA + dtx * B0.w; y += S[3] * C0.w;
        S[4] = S[4] * dA + dtx * B1.x; y += S[4] * C1.x;
        S[5] = S[5] * dA + dtx * B1.y; y += S[5] * C1.y;
        S[6] = S[6] * dA + dtx * B1.z; y += S[6] * C1.z;
        S[7] = S[7] * dA + dtx * B1.w; y += S[7] * C1.w;

        y += __shfl_xor_sync(0xFFFFFFFFu, y, 1);
        y += __shfl_xor_sync(0xFFFFFFFFu, y, 2);
        y += __shfl_xor_sync(0xFFFFFFFFu, y, 4);

        if (writer) {
            int pl = d ? (Lseq - 1 - t) : t;
            yb[(size_t)pl * DI + h * HD + p] = y + Dh * xv;
        }
    }
}

// ======================= gate + RMSNorm (+tf32 round of y) =======================
__global__ __launch_bounds__(256)
void gate_norm_kernel(const float* __restrict__ norm_w)
{
    const int idx = blockIdx.x;
    const int l = idx & (Lseq - 1);
    const int b = (idx >> 11) & 3;
    const int d = idx >> 13;

    float* yrow = g_y + ((size_t)(d * Bsz + b) * Lseq + l) * DI;
    const float* zrow = g_zxbcdt + ((size_t)b * Lseq + l) * DIP;

    float vals[8];
    float ss = 0.f;
#pragma unroll
    for (int i = 0; i < 8; i++) {
        int c = threadIdx.x + i * 256;
        float yv = yrow[c];
        float z = zrow[c];
        float g = yv * (z / (1.f + expf(-z)));
        vals[i] = g;
        ss += g * g;
    }

    __shared__ float red[8];
#pragma unroll
    for (int m = 16; m > 0; m >>= 1) ss += __shfl_xor_sync(0xFFFFFFFFu, ss, m);
    if ((threadIdx.x & 31) == 0) red[threadIdx.x >> 5] = ss;
    __syncthreads();
    if (threadIdx.x < 8) {
        float v = red[threadIdx.x];
#pragma unroll
        for (int m = 4; m > 0; m >>= 1) v += __shfl_xor_sync(0xFFu, v, m);
        if (threadIdx.x == 0) red[0] = v;
    }
    __syncthreads();
    float scale = rsqrtf(red[0] * (1.f / DI) + 1e-5f);

#pragma unroll
    for (int i = 0; i < 8; i++) {
        int c = threadIdx.x + i * 256;
        yrow[c] = roundtf(vals[i] * scale * norm_w[c]);
    }
}

// ======================= launch =======================
extern "C" void kernel_launch(void* const* d_in, const int* in_sizes, int n_in,
                              void* d_out, int out_size)
{
    const float* x          = (const float*)d_in[0];
    const float* in_proj_w  = (const float*)d_in[1];
    const float* conv_w     = (const float*)d_in[2];
    const float* conv_b     = (const float*)d_in[3];
    const float* dt_bias    = (const float*)d_in[4];
    const float* A_log      = (const float*)d_in[5];
    const float* Dvec       = (const float*)d_in[6];
    const float* norm_w     = (const float*)d_in[7];
    const float* out_proj_w = (const float*)d_in[8];
    const float* proj_w     = (const float*)d_in[9];
    const float* proj_b     = (const float*)d_in[10];
    float* out = (float*)d_out;

    float* zp;  cudaGetSymbolAddress((void**)&zp, g_zxbcdt);
    float* yp;  cudaGetSymbolAddress((void**)&yp, g_y);
    float* cp;  cudaGetSymbolAddress((void**)&cp, g_cat);
    float* xr;  cudaGetSymbolAddress((void**)&xr, g_xr);
    float* wT;  cudaGetSymbolAddress((void**)&wT, g_wT);

    float* inT   = wT;                          // [4256,1024]
    float* outT  = wT + 4256 * 1024;            // [1024,2048]
    float* projT = outT + 1024 * 2048;          // [1024,2048]

    cudaFuncSetAttribute(gemm_wmma<1024, false>, cudaFuncAttributeMaxDynamicSharedMemorySize, GEMM_SMEM);
    cudaFuncSetAttribute(gemm_wmma<2048, false>, cudaFuncAttributeMaxDynamicSharedMemorySize, GEMM_SMEM);
    cudaFuncSetAttribute(gemm_wmma<2048, true>,  cudaFuncAttributeMaxDynamicSharedMemorySize, GEMM_SMEM);

    dim3 tb(32, 8);
    transpose_kernel<<<dim3(DIP / 32, DM / 32), tb>>>(in_proj_w, inT, DM, DIP);
    transpose_kernel<<<dim3(DM / 32, DI / 32), tb>>>(out_proj_w, outT, DI, DM);
    transpose_kernel<<<dim3(DM / 32, DI / 32), tb>>>(proj_w, projT, 2 * DM, DM);
    round_kernel<<<(NTOK * DM) / 1024, 256>>>(x, xr);

    // 1) in_proj: zxbcdt[8192,4256] = xr @ inT^T
    gemm_wmma<1024, false><<<dim3((DIP + TNn - 1) / TNn, NTOK / TMm), 256, GEMM_SMEM>>>(
        xr, inT, zp, DIP, DIP);

    // 2) conv + silu + dt prep (8 timesteps per CTA)
    conv_silu_kernel<<<2 * Bsz * (Lseq / 8), 256>>>(conv_w, conv_b, dt_bias, A_log);

    // 3) selective scan
    scan_kernel<<<2 * Bsz * NH, 512>>>(Dvec);

    // 4) gate + RMSNorm (writes tf32-rounded y)
    gate_norm_kernel<<<2 * NTOK, 256>>>(norm_w);

    // 5) out_proj per direction into concat buffer (rounded for final GEMM)
    gemm_wmma<2048, true><<<dim3((DM + TNn - 1) / TNn, NTOK / TMm), 256, GEMM_SMEM>>>(
        yp, outT, cp, DM, 2 * DM);
    gemm_wmma<2048, true><<<dim3((DM + TNn - 1) / TNn, NTOK / TMm), 256, GEMM_SMEM>>>(
        yp + (size_t)NTOK * DI, outT, cp + DM, DM, 2 * DM);

    // 6) final projection, then bias add
    gemm_wmma<2048, false><<<dim3((DM + TNn - 1) / TNn, NTOK / TMm), 256, GEMM_SMEM>>>(
        cp, projT, out, DM, DM);
    bias_add_kernel<<<NTOK, 256>>>(out, proj_b);
}